// round 2
// baseline (speedup 1.0000x reference)
#include <cuda_runtime.h>

// Device scratch accumulator (no cudaMalloc allowed).
__device__ double g_sum;

__global__ void zero_kernel() {
    g_sum = 0.0;
}

// Grid-stride float4 squared-abs-diff reduction.
// sum += (in[i]-tg[i])^2   (|x|^2 == x^2, abs is free)
__global__ void reduce_kernel(const float* __restrict__ in,
                              const float* __restrict__ tg,
                              int n4) {
    const float4* __restrict__ in4 = (const float4*)in;
    const float4* __restrict__ tg4 = (const float4*)tg;

    float acc = 0.0f;
    int idx = blockIdx.x * blockDim.x + threadIdx.x;
    int stride = gridDim.x * blockDim.x;

    for (int i = idx; i < n4; i += stride) {
        float4 a = __ldg(&in4[i]);
        float4 b = __ldg(&tg4[i]);
        float dx = a.x - b.x;
        float dy = a.y - b.y;
        float dz = a.z - b.z;
        float dw = a.w - b.w;
        acc = fmaf(dx, dx, acc);
        acc = fmaf(dy, dy, acc);
        acc = fmaf(dz, dz, acc);
        acc = fmaf(dw, dw, acc);
    }

    // Warp reduction
    #pragma unroll
    for (int off = 16; off > 0; off >>= 1)
        acc += __shfl_xor_sync(0xFFFFFFFFu, acc, off);

    // Block reduction via shared memory
    __shared__ float warp_sums[32];
    int lane = threadIdx.x & 31;
    int wid  = threadIdx.x >> 5;
    if (lane == 0) warp_sums[wid] = acc;
    __syncthreads();

    if (wid == 0) {
        int nwarps = (blockDim.x + 31) >> 5;
        float v = (lane < nwarps) ? warp_sums[lane] : 0.0f;
        #pragma unroll
        for (int off = 16; off > 0; off >>= 1)
            v += __shfl_xor_sync(0xFFFFFFFFu, v, off);
        if (lane == 0)
            atomicAdd(&g_sum, (double)v);
    }
}

// Apply the element-0 conditional analytically and write the mean.
__global__ void finalize_kernel(const float* __restrict__ in,
                                const float* __restrict__ tg,
                                float* __restrict__ out,
                                int n) {
    float d0 = fabsf(in[0] - tg[0]);
    bool hit = (d0 == 3.0f) || (d0 == 4.0f) || (d0 == 5.0f) || (d0 == 6.0f);
    float d0a = hit ? d0 * 0.8f : d0;
    double s = g_sum - (double)d0 * (double)d0 + (double)d0a * (double)d0a;
    out[0] = (float)(s / (double)n);
}

extern "C" void kernel_launch(void* const* d_in, const int* in_sizes, int n_in,
                              void* d_out, int out_size) {
    const float* in = (const float*)d_in[0];
    const float* tg = (const float*)d_in[1];
    float* out = (float*)d_out;
    int n = in_sizes[0];
    int n4 = n >> 2;  // N = 32M, divisible by 4

    zero_kernel<<<1, 1>>>();

    const int threads = 256;
    int blocks = 4096;  // ~1M threads, 8 float4 iters each
    reduce_kernel<<<blocks, threads>>>(in, tg, n4);

    finalize_kernel<<<1, 1>>>(in, tg, out, n);
}